// round 14
// baseline (speedup 1.0000x reference)
#include <cuda_runtime.h>
#include <stdint.h>

namespace {

constexpr int BATCH = 64;
constexpr int INPUT = 784;
constexpr int HID   = 4096;
constexpr int T     = 30;
constexpr float DECAY = 0.99f;
constexpr float THR   = 0.5f;
constexpr float SCALE = 16.0f;
constexpr float INV30 = 1.0f / 30.0f;

constexpr int M  = T * BATCH;           // 1920
constexpr int W0 = (INPUT + 31) / 32;   // 25 mask words for layer-0 spikes
constexpr int W1N = HID / 32;           // 128 mask words for layer-1 spikes

// scratch (static device globals — referenced ONLY inside kernels)
__device__ float    g_cur1[(size_t)M * HID];
__device__ float    g_cur2[(size_t)M * HID];
__device__ uint32_t g_mask0[(size_t)M * W0];
__device__ uint32_t g_mask1[(size_t)M * W1N];
__device__ float    g_xmax;

__device__ __forceinline__ uint32_t s2u(const void* p) {
    return (uint32_t)__cvta_generic_to_shared(p);
}

// ---------------------------------------------------------------- max(x)
__global__ void k_max(const float* __restrict__ x) {
    __shared__ float sm[1024];
    float m = 0.f;
    for (int i = threadIdx.x; i < BATCH * INPUT; i += 1024) m = fmaxf(m, x[i]);
    sm[threadIdx.x] = m;
    __syncthreads();
    for (int s = 512; s > 0; s >>= 1) {
        if (threadIdx.x < s) sm[threadIdx.x] = fmaxf(sm[threadIdx.x], sm[threadIdx.x + s]);
        __syncthreads();
    }
    if (threadIdx.x == 0) g_xmax = fmaxf(sm[0], 1e-12f);
}

// ---------------------------------------------------------------- layer 0 LIF -> out0 + s0 bitmask
// thread = (batch, 32-pixel word)
__global__ void k_layer0(const float* __restrict__ x, float* __restrict__ out) {
    int tid = blockIdx.x * blockDim.x + threadIdx.x;
    if (tid >= BATCH * W0) return;
    int b = tid / W0, w = tid - b * W0;
    int base = w * 32;
    int nv = INPUT - base; if (nv > 32) nv = 32;

    float xs[32], v[32], sum[32];
#pragma unroll
    for (int e = 0; e < 32; e++) { xs[e] = 0.f; v[e] = 0.f; sum[e] = 0.f; }
    for (int e = 0; e < nv; e++)
        xs[e] = __fmul_rn(__fdiv_rn(x[b * INPUT + base + e], g_xmax), SCALE);

#pragma unroll 1
    for (int t = 0; t < T; t++) {
        uint32_t bits = 0;
#pragma unroll
        for (int e = 0; e < 32; e++) {
            float pre = __fadd_rn(__fmul_rn(v[e], DECAY), xs[e]);  // mul+add, no FMA
            bool sp = (pre >= THR);     // xs=0 lanes never reach 0.5
            v[e] = sp ? 0.f : pre;
            sum[e] += sp ? 1.f : 0.f;
            bits |= (sp ? 1u : 0u) << e;
        }
        g_mask0[(size_t)(t * BATCH + b) * W0 + w] = bits;
    }
    for (int e = 0; e < nv; e++)
        out[b * INPUT + base + e] = __fmul_rn(sum[e], INV30);
}

// ---------------------------------------------------------------- sparse ascending-k fp32 accumulate
// C[m][n] = sum over spiking k (ascending, single fp32 accumulator, RN) of W[k][n]
// Bit-exact replica of an fp32 FMA serial-K GEMM chain with a 0/1 A operand.
// LAYER selects the device-global mask/output buffers internally (host must
// not pass __device__ symbols as arguments).
template <int LAYER>
__global__ __launch_bounds__(512, 1) void k_sparse(const float* __restrict__ W) {
    constexpr int KROWS  = (LAYER == 1) ? INPUT : HID;
    constexpr int NWORDS = (LAYER == 1) ? W0 : W1N;
    const uint32_t* __restrict__ mask = (LAYER == 1) ? g_mask0 : g_mask1;
    float* __restrict__ C             = (LAYER == 1) ? g_cur1  : g_cur2;

    __shared__ float    wbuf[2][32 * 128];   // 2 x 16KB
    __shared__ uint32_t bits[2][128];

    const int tid = threadIdx.x;
    const int m0 = blockIdx.x * 128;
    const int n0 = blockIdx.y * 128;
    const int rg = tid >> 4;                  // 0..31, 4 rows each
    const int cg = tid & 15;                  // 8 cols (2 float4)

    float acc[4][8];
#pragma unroll
    for (int r = 0; r < 4; r++)
#pragma unroll
        for (int e = 0; e < 8; e++) acc[r][e] = 0.f;

    auto issue = [&](int buf, int kc) {
        int k0 = kc * 32;
#pragma unroll
        for (int i = 0; i < 2; i++) {
            int idx = tid + i * 512;
            int kr = idx >> 5, c4 = idx & 31;
            int row = k0 + kr;
            if (row > KROWS - 1) row = KROWS - 1;   // clamp (pad bits are zero)
            const float* src = W + (size_t)row * HID + n0 + c4 * 4;
            uint32_t dst = s2u(&wbuf[buf][kr * 128 + c4 * 4]);
            asm volatile("cp.async.cg.shared.global [%0],[%1],16;\n" ::"r"(dst), "l"(src));
        }
        if (tid < 128) {
            const uint32_t* src = &mask[(size_t)(m0 + tid) * NWORDS + kc];
            uint32_t dst = s2u(&bits[buf][tid]);
            asm volatile("cp.async.ca.shared.global [%0],[%1],4;\n" ::"r"(dst), "l"(src));
        }
        asm volatile("cp.async.commit_group;\n" ::);
    };

    issue(0, 0);

    for (int kc = 0; kc < NWORDS; kc++) {
        const int buf = kc & 1;
        if (kc + 1 < NWORDS) {
            issue(buf ^ 1, kc + 1);
            asm volatile("cp.async.wait_group 1;\n" ::);
        } else {
            asm volatile("cp.async.wait_group 0;\n" ::);
        }
        __syncthreads();

#pragma unroll
        for (int r = 0; r < 4; r++) {
            uint32_t wd = bits[buf][rg * 4 + r];
            while (wd) {
                int j = __ffs(wd) - 1;     // ascending k within word
                wd &= wd - 1;
                const float4* wp = reinterpret_cast<const float4*>(
                    &wbuf[buf][j * 128 + cg * 8]);
                float4 w0 = wp[0], w1 = wp[1];
                acc[r][0] = __fadd_rn(acc[r][0], w0.x);
                acc[r][1] = __fadd_rn(acc[r][1], w0.y);
                acc[r][2] = __fadd_rn(acc[r][2], w0.z);
                acc[r][3] = __fadd_rn(acc[r][3], w0.w);
                acc[r][4] = __fadd_rn(acc[r][4], w1.x);
                acc[r][5] = __fadd_rn(acc[r][5], w1.y);
                acc[r][6] = __fadd_rn(acc[r][6], w1.z);
                acc[r][7] = __fadd_rn(acc[r][7], w1.w);
            }
        }
        __syncthreads();
    }

#pragma unroll
    for (int r = 0; r < 4; r++) {
        size_t row = m0 + rg * 4 + r;
        float* Cp = &C[row * HID + n0 + cg * 8];
        reinterpret_cast<float4*>(Cp)[0] = make_float4(acc[r][0], acc[r][1], acc[r][2], acc[r][3]);
        reinterpret_cast<float4*>(Cp)[1] = make_float4(acc[r][4], acc[r][5], acc[r][6], acc[r][7]);
    }
}

// ---------------------------------------------------------------- layer-1 LIF scan -> out1 + s1 bitmask
__global__ void k_lif1_mask(float* __restrict__ out) {
    int tid = blockIdx.x * blockDim.x + threadIdx.x;
    if (tid >= BATCH * W1N) return;
    int b = tid >> 7, w = tid & 127;

    float v[32], sum[32];
#pragma unroll
    for (int i = 0; i < 32; i++) { v[i] = 0.f; sum[i] = 0.f; }

#pragma unroll 1
    for (int t = 0; t < T; t++) {
        const float4* cp = reinterpret_cast<const float4*>(
            &g_cur1[(size_t)(t * BATCH + b) * HID + w * 32]);
        uint32_t bits = 0;
#pragma unroll
        for (int q = 0; q < 8; q++) {
            float4 c = cp[q];
            float cv[4] = {c.x, c.y, c.z, c.w};
#pragma unroll
            for (int e = 0; e < 4; e++) {
                int i = q * 4 + e;
                float nv = __fadd_rn(__fmul_rn(v[i], DECAY), cv[e]);
                bool sp = (nv >= THR);
                v[i] = sp ? 0.f : nv;
                sum[i] += sp ? 1.f : 0.f;
                bits |= (sp ? 1u : 0u) << i;
            }
        }
        g_mask1[(size_t)(t * BATCH + b) * W1N + w] = bits;
    }
#pragma unroll
    for (int i = 0; i < 32; i++)
        out[(size_t)b * HID + w * 32 + i] = __fmul_rn(sum[i], INV30);
}

// ---------------------------------------------------------------- layer-2 LIF scan -> out2
__global__ void k_lif2(float* __restrict__ out) {
    int idx = blockIdx.x * blockDim.x + threadIdx.x;
    if (idx >= BATCH * HID) return;
    int b = idx >> 12, n = idx & 4095;
    float v = 0.f, sum = 0.f;
#pragma unroll 1
    for (int t = 0; t < T; t++) {
        float c = g_cur2[(size_t)(t * BATCH + b) * HID + n];
        v = __fadd_rn(__fmul_rn(v, DECAY), c);
        float s = (v >= THR) ? 1.f : 0.f;
        v = (v >= THR) ? 0.f : v;
        sum += s;
    }
    out[idx] = __fmul_rn(sum, INV30);
}

}  // namespace

extern "C" void kernel_launch(void* const* d_in, const int* in_sizes, int n_in,
                              void* d_out, int out_size) {
    const float* x  = (const float*)d_in[0];
    const float* W1 = (const float*)d_in[1];
    const float* W2 = (const float*)d_in[2];
    float* out = (float*)d_out;
    (void)in_sizes; (void)n_in; (void)out_size;

    k_max<<<1, 1024>>>(x);
    k_layer0<<<(BATCH * W0 + 255) / 256, 256>>>(x, out);

    // layer 1: cur1 = ascending-k fp32 chain over s0 spikes of W1 rows
    k_sparse<1><<<dim3(M / 128, HID / 128), 512>>>(W1);
    k_lif1_mask<<<(BATCH * W1N + 255) / 256, 256>>>(out + BATCH * INPUT);

    // layer 2: cur2 = ascending-k fp32 chain over s1 spikes of W2 rows
    k_sparse<2><<<dim3(M / 128, HID / 128), 512>>>(W2);
    k_lif2<<<(BATCH * HID + 255) / 256, 256>>>(out + BATCH * INPUT + BATCH * HID);
}

// round 15
// speedup vs baseline: 1.3545x; 1.3545x over previous
#include <cuda_runtime.h>
#include <stdint.h>

namespace {

constexpr int BATCH = 64;
constexpr int INPUT = 784;
constexpr int HID   = 4096;
constexpr int T     = 30;
constexpr float DECAY = 0.99f;
constexpr float THR   = 0.5f;
constexpr float SCALE = 16.0f;
constexpr float INV30 = 1.0f / 30.0f;

constexpr int M   = T * BATCH;           // 1920
constexpr int W0  = (INPUT + 31) / 32;   // 25 mask words (layer-0 spikes)
constexpr int W1N = HID / 32;            // 128 mask words (layer-1 spikes)

// scratch (static device globals — referenced ONLY inside kernels)
__device__ float    g_cur1[(size_t)M * HID];
__device__ float    g_cur2[(size_t)M * HID];
__device__ uint32_t g_mask0[(size_t)M * W0];
__device__ uint32_t g_mask1[(size_t)M * W1N];
__device__ float    g_xmax;

__device__ __forceinline__ uint32_t s2u(const void* p) {
    return (uint32_t)__cvta_generic_to_shared(p);
}

// ---------------------------------------------------------------- max(x)
__global__ void k_max(const float* __restrict__ x) {
    __shared__ float sm[1024];
    float m = 0.f;
    for (int i = threadIdx.x; i < BATCH * INPUT; i += 1024) m = fmaxf(m, x[i]);
    sm[threadIdx.x] = m;
    __syncthreads();
    for (int s = 512; s > 0; s >>= 1) {
        if (threadIdx.x < s) sm[threadIdx.x] = fmaxf(sm[threadIdx.x], sm[threadIdx.x + s]);
        __syncthreads();
    }
    if (threadIdx.x == 0) g_xmax = fmaxf(sm[0], 1e-12f);
}

// ---------------------------------------------------------------- layer 0 LIF -> out0 + s0 bitmask
__global__ void k_layer0(const float* __restrict__ x, float* __restrict__ out) {
    int tid = blockIdx.x * blockDim.x + threadIdx.x;
    if (tid >= BATCH * W0) return;
    int b = tid / W0, w = tid - b * W0;
    int base = w * 32;
    int nv = INPUT - base; if (nv > 32) nv = 32;

    float xs[32], v[32], sum[32];
#pragma unroll
    for (int e = 0; e < 32; e++) { xs[e] = 0.f; v[e] = 0.f; sum[e] = 0.f; }
    for (int e = 0; e < nv; e++)
        xs[e] = __fmul_rn(__fdiv_rn(x[b * INPUT + base + e], g_xmax), SCALE);

#pragma unroll 1
    for (int t = 0; t < T; t++) {
        uint32_t bits = 0;
#pragma unroll
        for (int e = 0; e < 32; e++) {
            float pre = __fadd_rn(__fmul_rn(v[e], DECAY), xs[e]);  // mul+add, no FMA
            bool sp = (pre >= THR);
            v[e] = sp ? 0.f : pre;
            sum[e] += sp ? 1.f : 0.f;
            bits |= (sp ? 1u : 0u) << e;
        }
        g_mask0[(size_t)(t * BATCH + b) * W0 + w] = bits;
    }
    for (int e = 0; e < nv; e++)
        out[b * INPUT + base + e] = __fmul_rn(sum[e], INV30);
}

// ---------------------------------------------------------------- sparse ascending-k fp32 accumulate (v2)
// C[m][n] = ascending-k single-fp32-accumulator RN chain of W[k][n] over spiking k.
// v2: warp-uniform rows (no divergence), conflict-free float4 lanes,
//     3-stage cp.async pipeline, 2 CTAs/SM.
template <int LAYER>
__global__ __launch_bounds__(512, 2) void k_sparse(const float* __restrict__ W) {
    constexpr int KROWS  = (LAYER == 1) ? INPUT : HID;
    constexpr int NWORDS = (LAYER == 1) ? W0 : W1N;
    const uint32_t* __restrict__ mask = (LAYER == 1) ? g_mask0 : g_mask1;
    float* __restrict__ C             = (LAYER == 1) ? g_cur1  : g_cur2;

    __shared__ float    wbuf[3][32 * 128];   // 3 x 16KB
    __shared__ uint32_t bits[3][128];

    const int tid  = threadIdx.x;
    const int wid  = tid >> 5;                // 16 warps: rows wid*8..wid*8+7
    const int lane = tid & 31;                // cols lane*4..lane*4+3
    const int m0 = blockIdx.x * 128;
    const int n0 = blockIdx.y * 128;

    float acc[8][4];
#pragma unroll
    for (int r = 0; r < 8; r++)
#pragma unroll
        for (int e = 0; e < 4; e++) acc[r][e] = 0.f;

    auto issue = [&](int buf, int kc) {
        int k0 = kc * 32;
#pragma unroll
        for (int i = 0; i < 2; i++) {
            int idx = tid + i * 512;          // 1024 float4 = 16KB
            int kr = idx >> 5, c4 = idx & 31;
            int row = k0 + kr;
            if (row > KROWS - 1) row = KROWS - 1;   // clamp (pad bits are zero)
            const float* src = W + (size_t)row * HID + n0 + c4 * 4;
            uint32_t dst = s2u(&wbuf[buf][kr * 128 + c4 * 4]);
            asm volatile("cp.async.cg.shared.global [%0],[%1],16;\n" ::"r"(dst), "l"(src));
        }
        if (tid < 128) {
            const uint32_t* src = &mask[(size_t)(m0 + tid) * NWORDS + kc];
            uint32_t dst = s2u(&bits[buf][tid]);
            asm volatile("cp.async.ca.shared.global [%0],[%1],4;\n" ::"r"(dst), "l"(src));
        }
        asm volatile("cp.async.commit_group;\n" ::);
    };

    issue(0, 0);
    issue(1, 1);   // NWORDS >= 2 for both layers

    for (int kc = 0; kc < NWORDS; kc++) {
        const int buf = kc % 3;
        if (kc + 1 < NWORDS) {
            asm volatile("cp.async.wait_group 1;\n" ::);
        } else {
            asm volatile("cp.async.wait_group 0;\n" ::);
        }
        __syncthreads();

        const float4* base = reinterpret_cast<const float4*>(&wbuf[buf][lane * 4]);
#pragma unroll 1
        for (int r = 0; r < 8; r++) {
            uint32_t wd = bits[buf][wid * 8 + r];   // warp-uniform
            while (wd) {
                int j = __ffs(wd) - 1;              // ascending k within word
                wd &= wd - 1;
                float4 w = base[j * 32];            // lane*16B stride: conflict-free
                acc[r][0] = __fadd_rn(acc[r][0], w.x);
                acc[r][1] = __fadd_rn(acc[r][1], w.y);
                acc[r][2] = __fadd_rn(acc[r][2], w.z);
                acc[r][3] = __fadd_rn(acc[r][3], w.w);
            }
        }
        __syncthreads();
        if (kc + 2 < NWORDS) issue((kc + 2) % 3, kc + 2);
    }

#pragma unroll
    for (int r = 0; r < 8; r++) {
        size_t row = m0 + wid * 8 + r;
        float* Cp = &C[row * HID + n0 + lane * 4];
        *reinterpret_cast<float4*>(Cp) = make_float4(acc[r][0], acc[r][1], acc[r][2], acc[r][3]);
    }
}

// ---------------------------------------------------------------- layer-1 LIF scan -> out1 + s1 bitmask
__global__ void k_lif1_mask(float* __restrict__ out) {
    int tid = blockIdx.x * blockDim.x + threadIdx.x;
    if (tid >= BATCH * W1N) return;
    int b = tid >> 7, w = tid & 127;

    float v[32], sum[32];
#pragma unroll
    for (int i = 0; i < 32; i++) { v[i] = 0.f; sum[i] = 0.f; }

#pragma unroll 1
    for (int t = 0; t < T; t++) {
        const float4* cp = reinterpret_cast<const float4*>(
            &g_cur1[(size_t)(t * BATCH + b) * HID + w * 32]);
        uint32_t bits = 0;
#pragma unroll
        for (int q = 0; q < 8; q++) {
            float4 c = cp[q];
            float cv[4] = {c.x, c.y, c.z, c.w};
#pragma unroll
            for (int e = 0; e < 4; e++) {
                int i = q * 4 + e;
                float nv = __fadd_rn(__fmul_rn(v[i], DECAY), cv[e]);
                bool sp = (nv >= THR);
                v[i] = sp ? 0.f : nv;
                sum[i] += sp ? 1.f : 0.f;
                bits |= (sp ? 1u : 0u) << i;
            }
        }
        g_mask1[(size_t)(t * BATCH + b) * W1N + w] = bits;
    }
#pragma unroll
    for (int i = 0; i < 32; i++)
        out[(size_t)b * HID + w * 32 + i] = __fmul_rn(sum[i], INV30);
}

// ---------------------------------------------------------------- layer-2 LIF scan -> out2
__global__ void k_lif2(float* __restrict__ out) {
    int idx = blockIdx.x * blockDim.x + threadIdx.x;
    if (idx >= BATCH * HID) return;
    int b = idx >> 12, n = idx & 4095;
    float v = 0.f, sum = 0.f;
#pragma unroll 1
    for (int t = 0; t < T; t++) {
        float c = g_cur2[(size_t)(t * BATCH + b) * HID + n];
        v = __fadd_rn(__fmul_rn(v, DECAY), c);
        float s = (v >= THR) ? 1.f : 0.f;
        v = (v >= THR) ? 0.f : v;
        sum += s;
    }
    out[idx] = __fmul_rn(sum, INV30);
}

}  // namespace

extern "C" void kernel_launch(void* const* d_in, const int* in_sizes, int n_in,
                              void* d_out, int out_size) {
    const float* x  = (const float*)d_in[0];
    const float* W1 = (const float*)d_in[1];
    const float* W2 = (const float*)d_in[2];
    float* out = (float*)d_out;
    (void)in_sizes; (void)n_in; (void)out_size;

    k_max<<<1, 1024>>>(x);
    k_layer0<<<(BATCH * W0 + 255) / 256, 256>>>(x, out);

    k_sparse<1><<<dim3(M / 128, HID / 128), 512>>>(W1);
    k_lif1_mask<<<(BATCH * W1N + 255) / 256, 256>>>(out + BATCH * INPUT);

    k_sparse<2><<<dim3(M / 128, HID / 128), 512>>>(W2);
    k_lif2<<<(BATCH * HID + 255) / 256, 256>>>(out + BATCH * INPUT + BATCH * HID);
}

// round 16
// speedup vs baseline: 2.5891x; 1.9114x over previous
#include <cuda_runtime.h>
#include <cuda_bf16.h>
#include <stdint.h>

namespace {

constexpr int BATCH = 64;
constexpr int INPUT = 784;
constexpr int HID   = 4096;
constexpr int T     = 30;
constexpr float DECAY = 0.99f;
constexpr float THR   = 0.5f;
constexpr float SCALE = 16.0f;
constexpr float INV30 = 1.0f / 30.0f;

constexpr int M   = T * BATCH;           // 1920
constexpr int W0  = (INPUT + 31) / 32;   // 25 mask words (layer-0 spikes)
constexpr int K2  = 3 * HID;             // 12288 (3 bf16 splits in K)

// scratch (static device globals — referenced ONLY inside kernels)
__device__ float         g_cur1[(size_t)M * HID];
__device__ float         g_cur2[(size_t)M * HID];
__device__ uint32_t      g_mask0[(size_t)M * W0];
__device__ __nv_bfloat16 g_A2[(size_t)M * K2];     // s1 spikes, K-tripled
__device__ __nv_bfloat16 g_B2[(size_t)K2 * HID];   // W2 3-way bf16 split
__device__ float         g_xmax;

__device__ __forceinline__ uint32_t s2u(const void* p) {
    return (uint32_t)__cvta_generic_to_shared(p);
}

// ---------------------------------------------------------------- max(x)
__global__ void k_max(const float* __restrict__ x) {
    __shared__ float sm[1024];
    float m = 0.f;
    for (int i = threadIdx.x; i < BATCH * INPUT; i += 1024) m = fmaxf(m, x[i]);
    sm[threadIdx.x] = m;
    __syncthreads();
    for (int s = 512; s > 0; s >>= 1) {
        if (threadIdx.x < s) sm[threadIdx.x] = fmaxf(sm[threadIdx.x], sm[threadIdx.x + s]);
        __syncthreads();
    }
    if (threadIdx.x == 0) g_xmax = fmaxf(sm[0], 1e-12f);
}

// ---------------------------------------------------------------- layer 0 LIF -> out0 + s0 bitmask
__global__ void k_layer0(const float* __restrict__ x, float* __restrict__ out) {
    int tid = blockIdx.x * blockDim.x + threadIdx.x;
    if (tid >= BATCH * W0) return;
    int b = tid / W0, w = tid - b * W0;
    int base = w * 32;
    int nv = INPUT - base; if (nv > 32) nv = 32;

    float xs[32], v[32], sum[32];
#pragma unroll
    for (int e = 0; e < 32; e++) { xs[e] = 0.f; v[e] = 0.f; sum[e] = 0.f; }
    for (int e = 0; e < nv; e++)
        xs[e] = __fmul_rn(__fdiv_rn(x[b * INPUT + base + e], g_xmax), SCALE);

#pragma unroll 1
    for (int t = 0; t < T; t++) {
        uint32_t bits = 0;
#pragma unroll
        for (int e = 0; e < 32; e++) {
            float pre = __fadd_rn(__fmul_rn(v[e], DECAY), xs[e]);  // mul+add, no FMA
            bool sp = (pre >= THR);
            v[e] = sp ? 0.f : pre;
            sum[e] += sp ? 1.f : 0.f;
            bits |= (sp ? 1u : 0u) << e;
        }
        g_mask0[(size_t)(t * BATCH + b) * W0 + w] = bits;
    }
    for (int e = 0; e < nv; e++)
        out[b * INPUT + base + e] = __fmul_rn(sum[e], INV30);
}

// ---------------------------------------------------------------- layer-1 sparse ascending-k fp32 chain (bit-exact)
__global__ __launch_bounds__(512, 2) void k_sparse1(const float* __restrict__ W) {
    constexpr int KROWS  = INPUT;
    constexpr int NWORDS = W0;
    const uint32_t* __restrict__ mask = g_mask0;
    float* __restrict__ C             = g_cur1;

    __shared__ float    wbuf[3][32 * 128];   // 3 x 16KB
    __shared__ uint32_t bits[3][128];

    const int tid  = threadIdx.x;
    const int wid  = tid >> 5;                // 16 warps: rows wid*8..wid*8+7
    const int lane = tid & 31;                // cols lane*4..lane*4+3
    const int m0 = blockIdx.x * 128;
    const int n0 = blockIdx.y * 128;

    float acc[8][4];
#pragma unroll
    for (int r = 0; r < 8; r++)
#pragma unroll
        for (int e = 0; e < 4; e++) acc[r][e] = 0.f;

    auto issue = [&](int buf, int kc) {
        int k0 = kc * 32;
#pragma unroll
        for (int i = 0; i < 2; i++) {
            int idx = tid + i * 512;
            int kr = idx >> 5, c4 = idx & 31;
            int row = k0 + kr;
            if (row > KROWS - 1) row = KROWS - 1;   // clamp (pad bits are zero)
            const float* src = W + (size_t)row * HID + n0 + c4 * 4;
            uint32_t dst = s2u(&wbuf[buf][kr * 128 + c4 * 4]);
            asm volatile("cp.async.cg.shared.global [%0],[%1],16;\n" ::"r"(dst), "l"(src));
        }
        if (tid < 128) {
            const uint32_t* src = &mask[(size_t)(m0 + tid) * NWORDS + kc];
            uint32_t dst = s2u(&bits[buf][tid]);
            asm volatile("cp.async.ca.shared.global [%0],[%1],4;\n" ::"r"(dst), "l"(src));
        }
        asm volatile("cp.async.commit_group;\n" ::);
    };

    issue(0, 0);
    issue(1, 1);

    for (int kc = 0; kc < NWORDS; kc++) {
        const int buf = kc % 3;
        if (kc + 1 < NWORDS) {
            asm volatile("cp.async.wait_group 1;\n" ::);
        } else {
            asm volatile("cp.async.wait_group 0;\n" ::);
        }
        __syncthreads();

        const float4* base = reinterpret_cast<const float4*>(&wbuf[buf][lane * 4]);
#pragma unroll 1
        for (int r = 0; r < 8; r++) {
            uint32_t wd = bits[buf][wid * 8 + r];   // warp-uniform
            while (wd) {
                int j = __ffs(wd) - 1;              // ascending k within word
                wd &= wd - 1;
                float4 w = base[j * 32];
                acc[r][0] = __fadd_rn(acc[r][0], w.x);
                acc[r][1] = __fadd_rn(acc[r][1], w.y);
                acc[r][2] = __fadd_rn(acc[r][2], w.z);
                acc[r][3] = __fadd_rn(acc[r][3], w.w);
            }
        }
        __syncthreads();
        if (kc + 2 < NWORDS) issue((kc + 2) % 3, kc + 2);
    }

#pragma unroll
    for (int r = 0; r < 8; r++) {
        size_t row = m0 + wid * 8 + r;
        float* Cp = &C[row * HID + n0 + lane * 4];
        *reinterpret_cast<float4*>(Cp) = make_float4(acc[r][0], acc[r][1], acc[r][2], acc[r][3]);
    }
}

// ---------------------------------------------------------------- layer-1 LIF -> out1 + A2 (K-tripled bf16 spikes)
// thread = (batch, group of 8 neurons): 32768 threads
__global__ void k_lif1_a2(float* __restrict__ out) {
    int tid = blockIdx.x * blockDim.x + threadIdx.x;
    if (tid >= BATCH * (HID / 8)) return;
    int b = tid >> 9, g = tid & 511;
    int n0 = g * 8;

    float v[8], sum[8];
#pragma unroll
    for (int i = 0; i < 8; i++) { v[i] = 0.f; sum[i] = 0.f; }

#pragma unroll 1
    for (int t = 0; t < T; t++) {
        const float4* cp = reinterpret_cast<const float4*>(
            &g_cur1[(size_t)(t * BATCH + b) * HID + n0]);
        float4 c0 = cp[0], c1 = cp[1];
        float cv[8] = {c0.x, c0.y, c0.z, c0.w, c1.x, c1.y, c1.z, c1.w};
        __nv_bfloat16* a2 = &g_A2[(size_t)(t * BATCH + b) * K2 + 3 * n0];
#pragma unroll
        for (int i = 0; i < 8; i++) {
            float nv = __fadd_rn(__fmul_rn(v[i], DECAY), cv[i]);
            bool sp = (nv >= THR);
            v[i] = sp ? 0.f : nv;
            sum[i] += sp ? 1.f : 0.f;
            __nv_bfloat16 sb = __float2bfloat16(sp ? 1.f : 0.f);
            a2[3 * i] = sb; a2[3 * i + 1] = sb; a2[3 * i + 2] = sb;
        }
    }
#pragma unroll
    for (int i = 0; i < 8; i++)
        out[(size_t)b * HID + n0 + i] = __fmul_rn(sum[i], INV30);
}

// ---------------------------------------------------------------- 3-way bf16 split of W2 -> g_B2
__global__ void k_split2(const float* __restrict__ W) {
    int i = blockIdx.x * blockDim.x + threadIdx.x;
    if (i >= HID * HID) return;
    int j = i / HID, n = i - j * HID;
    float w = W[i];
    __nv_bfloat16 h = __float2bfloat16(w);
    float r1 = w - __bfloat162float(h);
    __nv_bfloat16 mm = __float2bfloat16(r1);
    float r2 = r1 - __bfloat162float(mm);
    __nv_bfloat16 l = __float2bfloat16(r2);
    size_t base = (size_t)(3 * j) * HID + n;
    g_B2[base] = h; g_B2[base + HID] = mm; g_B2[base + 2 * HID] = l;
}

// ---------------------------------------------------------------- layer-2 GEMM: mma.sync bf16x3, fp32 accum
// cur2 = A2 @ B2 ; value-exact to ~1e-9/elt, reorder-class deviation only
// (proven flip-neutral in R2/R3/R4).
constexpr int BM = 128, BN = 128, BK = 32;
constexpr int LDA = BK + 8;    // 40
constexpr int LDB = BN + 8;    // 136

__global__ __launch_bounds__(256, 2) void k_gemm2() {
    constexpr int Kd = K2;
    const __nv_bfloat16* __restrict__ A  = g_A2;
    const __nv_bfloat16* __restrict__ Bm = g_B2;
    float* __restrict__ C = g_cur2;
    constexpr int Nc = HID;

    __shared__ __nv_bfloat16 As[2][BM * LDA];
    __shared__ __nv_bfloat16 Bs[2][BK * LDB];

    const int tid = threadIdx.x;
    const int lane = tid & 31;
    const int wid = tid >> 5;
    const int wm = wid & 3;
    const int wn = wid >> 2;
    const int bm0 = blockIdx.y * BM;
    const int bn0 = blockIdx.x * BN;

    float acc[2][8][4];
#pragma unroll
    for (int i = 0; i < 2; i++)
#pragma unroll
        for (int j = 0; j < 8; j++)
#pragma unroll
            for (int k = 0; k < 4; k++) acc[i][j][k] = 0.f;

    auto load_tile = [&](int buf, int k0) {
#pragma unroll
        for (int r = 0; r < 2; r++) {
            int c = tid + r * 256;
            int ar = c >> 2, ac = (c & 3) * 8;
            const __nv_bfloat16* gA = A + (size_t)(bm0 + ar) * Kd + (k0 + ac);
            uint32_t sA = s2u(&As[buf][ar * LDA + ac]);
            asm volatile("cp.async.cg.shared.global [%0],[%1],16;\n" ::"r"(sA), "l"(gA));
            int br = c >> 4, bc = (c & 15) * 8;
            const __nv_bfloat16* gB = Bm + (size_t)(k0 + br) * Nc + (bn0 + bc);
            uint32_t sB = s2u(&Bs[buf][br * LDB + bc]);
            asm volatile("cp.async.cg.shared.global [%0],[%1],16;\n" ::"r"(sB), "l"(gB));
        }
        asm volatile("cp.async.commit_group;\n" ::);
    };

    const int nk = Kd / BK;   // 384
    load_tile(0, 0);

    for (int kt = 0; kt < nk; kt++) {
        const int buf = kt & 1;
        if (kt + 1 < nk) {
            load_tile(buf ^ 1, (kt + 1) * BK);
            asm volatile("cp.async.wait_group 1;\n" ::);
        } else {
            asm volatile("cp.async.wait_group 0;\n" ::);
        }
        __syncthreads();

#pragma unroll
        for (int ks = 0; ks < 2; ks++) {
            uint32_t a[2][4];
#pragma unroll
            for (int mt = 0; mt < 2; mt++) {
                uint32_t ad = s2u(&As[buf][(wm * 32 + mt * 16 + (lane & 15)) * LDA +
                                           ks * 16 + (lane >> 4) * 8]);
                asm volatile("ldmatrix.sync.aligned.m8n8.x4.shared.b16 {%0,%1,%2,%3},[%4];\n"
                             : "=r"(a[mt][0]), "=r"(a[mt][1]), "=r"(a[mt][2]), "=r"(a[mt][3])
                             : "r"(ad));
            }
#pragma unroll
            for (int g = 0; g < 4; g++) {
                uint32_t bq[4];
                uint32_t bd = s2u(&Bs[buf][(ks * 16 + (lane & 15)) * LDB +
                                           wn * 64 + g * 16 + (lane >> 4) * 8]);
                asm volatile("ldmatrix.sync.aligned.m8n8.x4.trans.shared.b16 {%0,%1,%2,%3},[%4];\n"
                             : "=r"(bq[0]), "=r"(bq[1]), "=r"(bq[2]), "=r"(bq[3])
                             : "r"(bd));
#pragma unroll
                for (int h = 0; h < 2; h++) {
#pragma unroll
                    for (int mt = 0; mt < 2; mt++) {
                        float* d = acc[mt][g * 2 + h];
                        asm volatile(
                            "mma.sync.aligned.m16n8k16.row.col.f32.bf16.bf16.f32 "
                            "{%0,%1,%2,%3},{%4,%5,%6,%7},{%8,%9},{%0,%1,%2,%3};\n"
                            : "+f"(d[0]), "+f"(d[1]), "+f"(d[2]), "+f"(d[3])
                            : "r"(a[mt][0]), "r"(a[mt][1]), "r"(a[mt][2]), "r"(a[mt][3]),
                              "r"(bq[h * 2 + 0]), "r"(bq[h * 2 + 1]));
                    }
                }
            }
        }
        __syncthreads();
    }

#pragma unroll
    for (int mt = 0; mt < 2; mt++) {
#pragma unroll
        for (int nt = 0; nt < 8; nt++) {
            int row = bm0 + wm * 32 + mt * 16 + (lane >> 2);
            int col = bn0 + wn * 64 + nt * 8 + (lane & 3) * 2;
            float2 v0 = make_float2(acc[mt][nt][0], acc[mt][nt][1]);
            float2 v1 = make_float2(acc[mt][nt][2], acc[mt][nt][3]);
            *reinterpret_cast<float2*>(&C[(size_t)row * Nc + col]) = v0;
            *reinterpret_cast<float2*>(&C[(size_t)(row + 8) * Nc + col]) = v1;
        }
    }
}

// ---------------------------------------------------------------- layer-2 LIF scan -> out2
__global__ void k_lif2(float* __restrict__ out) {
    int idx = blockIdx.x * blockDim.x + threadIdx.x;
    if (idx >= BATCH * HID) return;
    int b = idx >> 12, n = idx & 4095;
    float v = 0.f, sum = 0.f;
#pragma unroll 1
    for (int t = 0; t < T; t++) {
        float c = g_cur2[(size_t)(t * BATCH + b) * HID + n];
        v = __fadd_rn(__fmul_rn(v, DECAY), c);
        float s = (v >= THR) ? 1.f : 0.f;
        v = (v >= THR) ? 0.f : v;
        sum += s;
    }
    out[idx] = __fmul_rn(sum, INV30);
}

}  // namespace

extern "C" void kernel_launch(void* const* d_in, const int* in_sizes, int n_in,
                              void* d_out, int out_size) {
    const float* x  = (const float*)d_in[0];
    const float* W1 = (const float*)d_in[1];
    const float* W2 = (const float*)d_in[2];
    float* out = (float*)d_out;
    (void)in_sizes; (void)n_in; (void)out_size;

    k_max<<<1, 1024>>>(x);
    k_layer0<<<(BATCH * W0 + 255) / 256, 256>>>(x, out);

    // layer 1: exact ascending-k fp32 chain (bit-exact s1 timing)
    k_sparse1<<<dim3(M / 128, HID / 128), 512>>>(W1);
    k_lif1_a2<<<(BATCH * (HID / 8) + 255) / 256, 256>>>(out + BATCH * INPUT);

    // layer 2: tensor-core bf16x3 GEMM (value-exact, reorder-class only)
    k_split2<<<(HID * HID + 255) / 256, 256>>>(W2);
    k_gemm2<<<dim3(HID / BN, M / BM), 256>>>();
    k_lif2<<<(BATCH * HID + 255) / 256, 256>>>(out + BATCH * INPUT + BATCH * HID);
}

// round 17
// speedup vs baseline: 4.5745x; 1.7668x over previous
#include <cuda_runtime.h>
#include <cuda_bf16.h>
#include <stdint.h>

namespace {

constexpr int BATCH = 64;
constexpr int INPUT = 784;
constexpr int HID   = 4096;
constexpr int T     = 30;
constexpr float DECAY = 0.99f;
constexpr float THR   = 0.5f;
constexpr float SCALE = 16.0f;
constexpr float INV30 = 1.0f / 30.0f;

constexpr int M   = T * BATCH;           // 1920
constexpr int W0  = (INPUT + 31) / 32;   // 25 words
constexpr int KP1 = 800;                 // K for layer-1 GEMM (784 padded to 25*32)
constexpr int K2  = 3 * HID;             // 12288

// scratch (static device globals — referenced ONLY inside kernels; zero-initialized,
// pad rows of g_s0T [784..800) are never written and stay 0.0f)
__device__ float         g_s0T[(size_t)KP1 * M];   // s0 transposed: [k][t*64+b], fp32 0/1
__device__ float         g_cur1[(size_t)M * HID];
__device__ float         g_cur2[(size_t)M * HID];
__device__ __nv_bfloat16 g_A2[(size_t)M * K2];     // s1 spikes, K-tripled
__device__ __nv_bfloat16 g_B2[(size_t)K2 * HID];   // W2 3-way bf16 split
__device__ float         g_xmax;

__device__ __forceinline__ uint32_t s2u(const void* p) {
    return (uint32_t)__cvta_generic_to_shared(p);
}

// ---------------------------------------------------------------- max(x)
__global__ void k_max(const float* __restrict__ x) {
    __shared__ float sm[1024];
    float m = 0.f;
    for (int i = threadIdx.x; i < BATCH * INPUT; i += 1024) m = fmaxf(m, x[i]);
    sm[threadIdx.x] = m;
    __syncthreads();
    for (int s = 512; s > 0; s >>= 1) {
        if (threadIdx.x < s) sm[threadIdx.x] = fmaxf(sm[threadIdx.x], sm[threadIdx.x + s]);
        __syncthreads();
    }
    if (threadIdx.x == 0) g_xmax = fmaxf(sm[0], 1e-12f);
}

// ---------------------------------------------------------------- layer 0 LIF -> out0 + s0T (fp32 0/1, transposed)
// thread = (word w, batch b); warp spans consecutive b -> coalesced s0T writes
__global__ void k_layer0(const float* __restrict__ x, float* __restrict__ out) {
    int tid = blockIdx.x * blockDim.x + threadIdx.x;
    if (tid >= W0 * BATCH) return;
    int w = tid / BATCH, b = tid - w * BATCH;
    int base = w * 32;
    int nv = INPUT - base; if (nv > 32) nv = 32;

    float xs[32], v[32], sum[32];
#pragma unroll
    for (int e = 0; e < 32; e++) { xs[e] = 0.f; v[e] = 0.f; sum[e] = 0.f; }
    for (int e = 0; e < nv; e++)
        xs[e] = __fmul_rn(__fdiv_rn(x[b * INPUT + base + e], g_xmax), SCALE);

#pragma unroll 1
    for (int t = 0; t < T; t++) {
        int col = t * BATCH + b;
#pragma unroll
        for (int e = 0; e < 32; e++) {
            float pre = __fadd_rn(__fmul_rn(v[e], DECAY), xs[e]);  // mul+add, no FMA
            bool sp = (pre >= THR);
            v[e] = sp ? 0.f : pre;
            sum[e] += sp ? 1.f : 0.f;
            if (e < nv)
                g_s0T[(size_t)(base + e) * M + col] = sp ? 1.f : 0.f;
        }
    }
    for (int e = 0; e < nv; e++)
        out[b * INPUT + base + e] = __fmul_rn(sum[e], INV30);
}

// ---------------------------------------------------------------- layer-1 dense FFMA GEMM (bit-exact ascending chain)
// cur1[m][n] = chain over k=0..799 of fma(s0T[k][m], W1[k][n], acc):
// s in {0,1} => each step is RN(acc+w) or exact no-op — bit-identical to the
// reference fp32 serial-K chain.
constexpr int LDT = 132;   // smem row pitch (floats)

__global__ __launch_bounds__(256, 2) void k_dense1(const float* __restrict__ W1) {
    __shared__ float as[2][32 * LDT];   // [kk][m]
    __shared__ float ws[2][32 * LDT];   // [kk][n]

    const int tid = threadIdx.x;
    const int rg = tid >> 4;     // 0..15: rows rg*8..+7
    const int cg = tid & 15;     // cols cg*8..+7
    const int m0 = blockIdx.x * 128;
    const int n0 = blockIdx.y * 128;

    float acc[8][8];
#pragma unroll
    for (int r = 0; r < 8; r++)
#pragma unroll
        for (int c = 0; c < 8; c++) acc[r][c] = 0.f;

    auto load = [&](int buf, int kc) {
        int k0 = kc * 32;
#pragma unroll
        for (int i = 0; i < 4; i++) {
            int idx = tid + i * 256;          // 1024 float4
            int kr = idx >> 5, c4 = idx & 31;
            const float* srcA = &g_s0T[(size_t)(k0 + kr) * M + m0 + c4 * 4];
            asm volatile("cp.async.cg.shared.global [%0],[%1],16;\n"
                         ::"r"(s2u(&as[buf][kr * LDT + c4 * 4])), "l"(srcA));
            int row = k0 + kr; if (row > INPUT - 1) row = INPUT - 1;  // a=0 there
            const float* srcW = W1 + (size_t)row * HID + n0 + c4 * 4;
            asm volatile("cp.async.cg.shared.global [%0],[%1],16;\n"
                         ::"r"(s2u(&ws[buf][kr * LDT + c4 * 4])), "l"(srcW));
        }
        asm volatile("cp.async.commit_group;\n" ::);
    };

    constexpr int NKC = KP1 / 32;   // 25
    load(0, 0);

    for (int kc = 0; kc < NKC; kc++) {
        const int buf = kc & 1;
        if (kc + 1 < NKC) {
            load(buf ^ 1, kc + 1);
            asm volatile("cp.async.wait_group 1;\n" ::);
        } else {
            asm volatile("cp.async.wait_group 0;\n" ::);
        }
        __syncthreads();

#pragma unroll 8
        for (int kk = 0; kk < 32; kk++) {
            float4 a0 = *reinterpret_cast<const float4*>(&as[buf][kk * LDT + rg * 8]);
            float4 a1 = *reinterpret_cast<const float4*>(&as[buf][kk * LDT + rg * 8 + 4]);
            float4 w0 = *reinterpret_cast<const float4*>(&ws[buf][kk * LDT + cg * 8]);
            float4 w1 = *reinterpret_cast<const float4*>(&ws[buf][kk * LDT + cg * 8 + 4]);
            float av[8] = {a0.x, a0.y, a0.z, a0.w, a1.x, a1.y, a1.z, a1.w};
            float wv[8] = {w0.x, w0.y, w0.z, w0.w, w1.x, w1.y, w1.z, w1.w};
#pragma unroll
            for (int r = 0; r < 8; r++)
#pragma unroll
                for (int c = 0; c < 8; c++)
                    acc[r][c] = __fmaf_rn(av[r], wv[c], acc[r][c]);
        }
        __syncthreads();
    }

#pragma unroll
    for (int r = 0; r < 8; r++) {
        float* Cp = &g_cur1[(size_t)(m0 + rg * 8 + r) * HID + n0 + cg * 8];
        *reinterpret_cast<float4*>(Cp)     = make_float4(acc[r][0], acc[r][1], acc[r][2], acc[r][3]);
        *reinterpret_cast<float4*>(Cp + 4) = make_float4(acc[r][4], acc[r][5], acc[r][6], acc[r][7]);
    }
}

// ---------------------------------------------------------------- layer-1 LIF -> out1 + A2 (K-tripled bf16)
// thread = (batch, 4 neurons); prefetch t+1
__global__ void k_lif1_a2(float* __restrict__ out) {
    int tid = blockIdx.x * blockDim.x + threadIdx.x;
    if (tid >= BATCH * (HID / 4)) return;
    int b = tid >> 10, g = tid & 1023;
    int n0 = g * 4;

    float v[4] = {0.f, 0.f, 0.f, 0.f}, sum[4] = {0.f, 0.f, 0.f, 0.f};

    float4 c = *reinterpret_cast<const float4*>(&g_cur1[(size_t)b * HID + n0]);
#pragma unroll 1
    for (int t = 0; t < T; t++) {
        float4 cn = (t + 1 < T)
            ? *reinterpret_cast<const float4*>(&g_cur1[(size_t)((t + 1) * BATCH + b) * HID + n0])
            : c;
        float cv[4] = {c.x, c.y, c.z, c.w};
        uint32_t u[4];
#pragma unroll
        for (int i = 0; i < 4; i++) {
            float nv = __fadd_rn(__fmul_rn(v[i], DECAY), cv[i]);
            bool sp = (nv >= THR);
            v[i] = sp ? 0.f : nv;
            sum[i] += sp ? 1.f : 0.f;
            u[i] = sp ? 0x3F80u : 0u;      // bf16(1.0) bits
        }
        uint2* a2 = reinterpret_cast<uint2*>(&g_A2[(size_t)(t * BATCH + b) * K2 + 3 * n0]);
        a2[0] = make_uint2(u[0] | (u[0] << 16), u[0] | (u[1] << 16));
        a2[1] = make_uint2(u[1] | (u[1] << 16), u[2] | (u[2] << 16));
        a2[2] = make_uint2(u[2] | (u[3] << 16), u[3] | (u[3] << 16));
        c = cn;
    }
    *reinterpret_cast<float4*>(&out[(size_t)b * HID + n0]) =
        make_float4(__fmul_rn(sum[0], INV30), __fmul_rn(sum[1], INV30),
                    __fmul_rn(sum[2], INV30), __fmul_rn(sum[3], INV30));
}

// ---------------------------------------------------------------- 3-way bf16 split of W2 -> g_B2
__global__ void k_split2(const float* __restrict__ W) {
    int i = blockIdx.x * blockDim.x + threadIdx.x;
    if (i >= HID * HID) return;
    int j = i / HID, n = i - j * HID;
    float w = W[i];
    __nv_bfloat16 h = __float2bfloat16(w);
    float r1 = w - __bfloat162float(h);
    __nv_bfloat16 mm = __float2bfloat16(r1);
    float r2 = r1 - __bfloat162float(mm);
    __nv_bfloat16 l = __float2bfloat16(r2);
    size_t base = (size_t)(3 * j) * HID + n;
    g_B2[base] = h; g_B2[base + HID] = mm; g_B2[base + 2 * HID] = l;
}

// ---------------------------------------------------------------- layer-2 GEMM: mma.sync bf16x3, fp32 accum (unchanged)
constexpr int BM = 128, BN = 128, BK = 32;
constexpr int LDA = BK + 8;
constexpr int LDB = BN + 8;

__global__ __launch_bounds__(256, 2) void k_gemm2() {
    constexpr int Kd = K2;
    const __nv_bfloat16* __restrict__ A  = g_A2;
    const __nv_bfloat16* __restrict__ Bm = g_B2;
    float* __restrict__ C = g_cur2;
    constexpr int Nc = HID;

    __shared__ __nv_bfloat16 As[2][BM * LDA];
    __shared__ __nv_bfloat16 Bs[2][BK * LDB];

    const int tid = threadIdx.x;
    const int lane = tid & 31;
    const int wid = tid >> 5;
    const int wm = wid & 3;
    const int wn = wid >> 2;
    const int bm0 = blockIdx.y * BM;
    const int bn0 = blockIdx.x * BN;

    float acc[2][8][4];
#pragma unroll
    for (int i = 0; i < 2; i++)
#pragma unroll
        for (int j = 0; j < 8; j++)
#pragma unroll
            for (int k = 0; k < 4; k++) acc[i][j][k] = 0.f;

    auto load_tile = [&](int buf, int k0) {
#pragma unroll
        for (int r = 0; r < 2; r++) {
            int c = tid + r * 256;
            int ar = c >> 2, ac = (c & 3) * 8;
            const __nv_bfloat16* gA = A + (size_t)(bm0 + ar) * Kd + (k0 + ac);
            asm volatile("cp.async.cg.shared.global [%0],[%1],16;\n"
                         ::"r"(s2u(&As[buf][ar * LDA + ac])), "l"(gA));
            int br = c >> 4, bc = (c & 15) * 8;
            const __nv_bfloat16* gB = Bm + (size_t)(k0 + br) * Nc + (bn0 + bc);
            asm volatile("cp.async.cg.shared.global [%0],[%1],16;\n"
                         ::"r"(s2u(&Bs[buf][br * LDB + bc])), "l"(gB));
        }
        asm volatile("cp.async.commit_group;\n" ::);
    };

    const int nk = Kd / BK;
    load_tile(0, 0);

    for (int kt = 0; kt < nk; kt++) {
        const int buf = kt & 1;
        if (kt + 1 < nk) {
            load_tile(buf ^ 1, (kt + 1) * BK);
            asm volatile("cp.async.wait_group 1;\n" ::);
        } else {
            asm volatile("cp.async.wait_group 0;\n" ::);
        }
        __syncthreads();

#pragma unroll
        for (int ks = 0; ks < 2; ks++) {
            uint32_t a[2][4];
#pragma unroll
            for (int mt = 0; mt < 2; mt++) {
                uint32_t ad = s2u(&As[buf][(wm * 32 + mt * 16 + (lane & 15)) * LDA +
                                           ks * 16 + (lane >> 4) * 8]);
                asm volatile("ldmatrix.sync.aligned.m8n8.x4.shared.b16 {%0,%1,%2,%3},[%4];\n"
                             : "=r"(a[mt][0]), "=r"(a[mt][1]), "=r"(a[mt][2]), "=r"(a[mt][3])
                             : "r"(ad));
            }
#pragma unroll
            for (int g = 0; g < 4; g++) {
                uint32_t bq[4];
                uint32_t bd = s2u(&Bs[buf][(ks * 16 + (lane & 15)) * LDB +
                                           wn * 64 + g * 16 + (lane >> 4) * 8]);
                asm volatile("ldmatrix.sync.aligned.m8n8.x4.trans.shared.b16 {%0,%1,%2,%3},[%4];\n"
                             : "=r"(bq[0]), "=r"(bq[1]), "=r"(bq[2]), "=r"(bq[3])
                             : "r"(bd));
#pragma unroll
                for (int h = 0; h < 2; h++) {
#pragma unroll
                    for (int mt = 0; mt < 2; mt++) {
                        float* d = acc[mt][g * 2 + h];
                        asm volatile(
                            "mma.sync.aligned.m16n8k16.row.col.f32.bf16.bf16.f32 "
                            "{%0,%1,%2,%3},{%4,%5,%6,%7},{%8,%9},{%0,%1,%2,%3};\n"
                            : "+f"(d[0]), "+f"(d[1]), "+f"(d[2]), "+f"(d[3])
                            : "r"(a[mt][0]), "r"(a[mt][1]), "r"(a[mt][2]), "r"(a[mt][3]),
                              "r"(bq[h * 2 + 0]), "r"(bq[h * 2 + 1]));
                    }
                }
            }
        }
        __syncthreads();
    }

#pragma unroll
    for (int mt = 0; mt < 2; mt++) {
#pragma unroll
        for (int nt = 0; nt < 8; nt++) {
            int row = bm0 + wm * 32 + mt * 16 + (lane >> 2);
            int col = bn0 + wn * 64 + nt * 8 + (lane & 3) * 2;
            float2 v0 = make_float2(acc[mt][nt][0], acc[mt][nt][1]);
            float2 v1 = make_float2(acc[mt][nt][2], acc[mt][nt][3]);
            *reinterpret_cast<float2*>(&C[(size_t)row * Nc + col]) = v0;
            *reinterpret_cast<float2*>(&C[(size_t)(row + 8) * Nc + col]) = v1;
        }
    }
}

// ---------------------------------------------------------------- layer-2 LIF scan -> out2 (4 neurons/thread, prefetch)
__global__ void k_lif2(float* __restrict__ out) {
    int tid = blockIdx.x * blockDim.x + threadIdx.x;
    if (tid >= BATCH * (HID / 4)) return;
    int b = tid >> 10, g = tid & 1023;
    int n0 = g * 4;

    float v[4] = {0.f, 0.f, 0.f, 0.f}, sum[4] = {0.f, 0.f, 0.f, 0.f};
    float4 c = *reinterpret_cast<const float4*>(&g_cur2[(size_t)b * HID + n0]);
#pragma unroll 1
    for (int t = 0; t < T; t++) {
        float4 cn = (t + 1 < T)
            ? *reinterpret_cast<const float4*>(&g_cur2[(size_t)((t + 1) * BATCH + b) * HID + n0])
            : c;
        float cv[4] = {c.x, c.y, c.z, c.w};
#pragma unroll
        for (int i = 0; i < 4; i++) {
            float nv = __fadd_rn(__fmul_rn(v[i], DECAY), cv[i]);
            bool sp = (nv >= THR);
            v[i] = sp ? 0.f : nv;
            sum[i] += sp ? 1.f : 0.f;
        }
        c = cn;
    }
    *reinterpret_cast<float4*>(&out[(size_t)b * HID + n0]) =
        make_float4(__fmul_rn(sum[0], INV30), __fmul_rn(sum[1], INV30),
                    __fmul_rn(sum[2], INV30), __fmul_rn(sum[3], INV30));
}

}  // namespace

extern "C" void kernel_launch(void* const* d_in, const int* in_sizes, int n_in,
                              void* d_out, int out_size) {
    const float* x  = (const float*)d_in[0];
    const float* W1 = (const float*)d_in[1];
    const float* W2 = (const float*)d_in[2];
    float* out = (float*)d_out;
    (void)in_sizes; (void)n_in; (void)out_size;

    k_max<<<1, 1024>>>(x);
    k_layer0<<<(W0 * BATCH + 255) / 256, 256>>>(x, out);

    // layer 1: dense FFMA GEMM, bit-exact ascending chain
    k_dense1<<<dim3(M / 128, HID / 128), 256>>>(W1);
    k_lif1_a2<<<(BATCH * (HID / 4) + 255) / 256, 256>>>(out + BATCH * INPUT);

    // layer 2: tensor-core bf16x3 GEMM (unchanged; keeps rel_err at 6.07e-4)
    k_split2<<<(HID * HID + 255) / 256, 256>>>(W2);
    k_gemm2<<<dim3(HID / BN, M / BM), 256>>>();
    k_lif2<<<(BATCH * (HID / 4) + 255) / 256, 256>>>(out + BATCH * INPUT + BATCH * HID);
}